// round 7
// baseline (speedup 1.0000x reference)
#include <cuda_runtime.h>
#include <cuda_bf16.h>
#include <math.h>
#include <stdint.h>

// Problem constants
#define NP_   1024
#define MNP_  4096
#define BS_   4
#define DIM_  512
#define NH_   8
#define DH_   64
#define TOPK_ 32

#define MROWS_Q  (NP_*BS_)                 // 4096
#define MROWS_KV (MNP_*BS_)                // 16384
#define MTOT     (MROWS_Q + 2*MROWS_KV)    // 36864

// ---------------------------------------------------------------------------
// Scratch (device globals; no allocation allowed)
// ---------------------------------------------------------------------------
__device__ __nv_bfloat16 g_ahi[(size_t)MTOT * DIM_];
__device__ __nv_bfloat16 g_alo[(size_t)MTOT * DIM_];
__device__ __nv_bfloat16 g_whi[3 * DIM_ * DIM_];
__device__ __nv_bfloat16 g_wlo[3 * DIM_ * DIM_];
__device__ float         g_proj[(size_t)MTOT * DIM_];

// ---------------------------------------------------------------------------
// Helpers
// ---------------------------------------------------------------------------
__device__ __forceinline__ uint32_t smem_u32(const void* p) {
    uint32_t a;
    asm("{ .reg .u64 t; cvta.to.shared.u64 t, %1; cvt.u32.u64 %0, t; }"
        : "=r"(a) : "l"(p));
    return a;
}

__device__ __forceinline__ void cp16(uint32_t dst, const void* src) {
    asm volatile("cp.async.cg.shared.global [%0], [%1], 16;\n"
                 :: "r"(dst), "l"(src) : "memory");
}

__device__ __forceinline__ uint32_t swz(uint32_t o) { return o ^ ((o >> 3) & 0x70); }

__device__ __forceinline__ void ldsm4(uint32_t* f, uint32_t addr) {
    asm volatile("ldmatrix.sync.aligned.m8n8.x4.shared.b16 {%0,%1,%2,%3}, [%4];"
                 : "=r"(f[0]), "=r"(f[1]), "=r"(f[2]), "=r"(f[3]) : "r"(addr));
}

__device__ __forceinline__ void mma16816(float* d, const uint32_t* a,
                                         const uint32_t* b) {
    asm volatile(
        "mma.sync.aligned.m16n8k16.row.col.f32.bf16.bf16.f32 "
        "{%0,%1,%2,%3}, {%4,%5,%6,%7}, {%8,%9}, {%0,%1,%2,%3};"
        : "+f"(d[0]), "+f"(d[1]), "+f"(d[2]), "+f"(d[3])
        : "r"(a[0]), "r"(a[1]), "r"(a[2]), "r"(a[3]), "r"(b[0]), "r"(b[1]));
}

// ---------------------------------------------------------------------------
// Fused split: fp32 -> (bf16 hi, bf16 lo) over q|k|v -> g_ahi/g_alo and
// W1|W2|W3 -> g_whi/g_wlo, in one launch.
// Region boundaries in float4 units.
// ---------------------------------------------------------------------------
#define R_Q  (MROWS_Q * DIM_ / 4)                 // 524288
#define R_K  (R_Q + MROWS_KV * DIM_ / 4)          // 2621440
#define R_V  (R_K + MROWS_KV * DIM_ / 4)          // 4718592
#define R_W1 (R_V + DIM_ * DIM_ / 4)              // +65536
#define R_W2 (R_W1 + DIM_ * DIM_ / 4)
#define R_W3 (R_W2 + DIM_ * DIM_ / 4)             // 4915200 total

__global__ __launch_bounds__(256)
void split_all(const float* __restrict__ q, const float* __restrict__ k,
               const float* __restrict__ v, const float* __restrict__ W1,
               const float* __restrict__ W2, const float* __restrict__ W3,
               __nv_bfloat16* __restrict__ ahi, __nv_bfloat16* __restrict__ alo,
               __nv_bfloat16* __restrict__ whi, __nv_bfloat16* __restrict__ wlo) {
    const int i = blockIdx.x * 256 + threadIdx.x;
    if (i >= R_W3) return;
    const float* src;
    __nv_bfloat16 *dh, *dl;
    size_t si, di;
    if (i < R_V) {                           // A-side: dst offset = i
        di = (size_t)i;
        dh = ahi; dl = alo;
        if (i < R_Q)      { src = q; si = (size_t)i; }
        else if (i < R_K) { src = k; si = (size_t)(i - R_Q); }
        else              { src = v; si = (size_t)(i - R_K); }
    } else {                                 // W-side: dst offset = i - R_V
        di = (size_t)(i - R_V);
        dh = whi; dl = wlo;
        if (i < R_W1)      { src = W1; si = (size_t)(i - R_V); }
        else if (i < R_W2) { src = W2; si = (size_t)(i - R_W1); }
        else               { src = W3; si = (size_t)(i - R_W2); }
    }
    float4 x = ((const float4*)src)[si];
    float val[4] = {x.x, x.y, x.z, x.w};
    __nv_bfloat16 h[4], l[4];
#pragma unroll
    for (int j = 0; j < 4; j++) {
        h[j] = __float2bfloat16(val[j]);
        l[j] = __float2bfloat16(val[j] - __bfloat162float(h[j]));
    }
    *(uint2*)(dh + 4 * di) = *(uint2*)h;
    *(uint2*)(dl + 4 * di) = *(uint2*)l;
}

// ---------------------------------------------------------------------------
// mma.sync split-bf16 GEMM (unchanged from R4): out = A*W^T + bias
// ---------------------------------------------------------------------------
#define KC       64
#define NCHUNK   24
#define STAGES   3
#define A_BYTES  (128 * 128)
#define B_BYTES  (128 * 128)
#define STG_B    (A_BYTES + B_BYTES)
#define GEMM_SMEM (STAGES * STG_B)           // 96KB

__global__ __launch_bounds__(256)
void gemm_mma(const __nv_bfloat16* __restrict__ ahi,
              const __nv_bfloat16* __restrict__ alo,
              const __nv_bfloat16* __restrict__ whi,
              const __nv_bfloat16* __restrict__ wlo,
              const float* __restrict__ b1, const float* __restrict__ b2,
              const float* __restrict__ b3, float* __restrict__ out) {
    extern __shared__ __align__(1024) char smem[];
    const uint32_t sbase = smem_u32(smem);
    const int tid = threadIdx.x;
    const int wid = tid >> 5;
    const int lane = tid & 31;
    const int wm = wid & 3;
    const int wn = wid >> 2;

    const int n0blk = blockIdx.x * 128;
    const int mt = blockIdx.y;
    const int widx = (mt < 32) ? 0 : (mt < 160) ? 1 : 2;
    const float* bias = (widx == 0) ? b1 : (widx == 1) ? b2 : b3;
    const __nv_bfloat16* Whi = whi + (size_t)widx * DIM_ * DIM_;
    const __nv_bfloat16* Wlo = wlo + (size_t)widx * DIM_ * DIM_;
    const size_t arow0 = (size_t)mt * 128;

    float acc[2][8][4];
#pragma unroll
    for (int i = 0; i < 2; i++)
#pragma unroll
        for (int j = 0; j < 8; j++)
#pragma unroll
            for (int r = 0; r < 4; r++) acc[i][j][r] = 0.f;

    auto load_chunk = [&](int c, int s) {
        const int t  = c >> 3;
        const int kk = (c & 7) * KC;
        const __nv_bfloat16* Ap = (t < 2) ? ahi : alo;
        const __nv_bfloat16* Bp = (t == 1) ? Wlo : Whi;
        const uint32_t a_s = sbase + s * STG_B;
        const uint32_t b_s = a_s + A_BYTES;
#pragma unroll
        for (int i = 0; i < 4; i++) {
            int u = tid + (i << 8);
            int r = u >> 3, j = u & 7;
            cp16(a_s + swz(r * 128 + j * 16),
                 Ap + (arow0 + r) * DIM_ + kk + j * 8);
        }
#pragma unroll
        for (int i = 0; i < 4; i++) {
            int u = tid + (i << 8);
            int r = u >> 3, j = u & 7;
            cp16(b_s + swz(r * 128 + j * 16),
                 Bp + (size_t)(n0blk + r) * DIM_ + kk + j * 8);
        }
        asm volatile("cp.async.commit_group;\n" ::: "memory");
    };

    load_chunk(0, 0);
    load_chunk(1, 1);

    const int a_row = wm * 32 + (lane & 15);
    const int a_ch  = (lane >> 4);
    const int b_row = wn * 64 + (lane & 7) + ((lane >> 4) << 3);
    const int b_ch  = ((lane >> 3) & 1);

#pragma unroll 1
    for (int c = 0; c < NCHUNK; ++c) {
        const int s = c % STAGES;
        if (c == NCHUNK - 1)
            asm volatile("cp.async.wait_group 0;\n" ::: "memory");
        else
            asm volatile("cp.async.wait_group 1;\n" ::: "memory");
        __syncthreads();
        if (c + 2 < NCHUNK) load_chunk(c + 2, (c + 2) % STAGES);

        const uint32_t a_s = sbase + s * STG_B;
        const uint32_t b_s = a_s + A_BYTES;
#pragma unroll
        for (int ks = 0; ks < 4; ks++) {
            const int c0 = ks * 2;
            uint32_t af[2][4];
#pragma unroll
            for (int i = 0; i < 2; i++)
                ldsm4(af[i], a_s + swz((a_row + i * 16) * 128 + (c0 + a_ch) * 16));
            uint32_t bf[4][4];
#pragma unroll
            for (int j = 0; j < 4; j++)
                ldsm4(bf[j], b_s + swz((b_row + j * 16) * 128 + (c0 + b_ch) * 16));
#pragma unroll
            for (int i = 0; i < 2; i++)
#pragma unroll
                for (int j = 0; j < 4; j++) {
                    mma16816(acc[i][2 * j],     af[i], &bf[j][0]);
                    mma16816(acc[i][2 * j + 1], af[i], &bf[j][2]);
                }
        }
    }

    const int lr = lane >> 2;
    const int lc = (lane & 3) * 2;
#pragma unroll
    for (int i = 0; i < 2; i++) {
        const size_t row0 = arow0 + wm * 32 + i * 16 + lr;
#pragma unroll
        for (int j = 0; j < 8; j++) {
            const int col = n0blk + wn * 64 + j * 8 + lc;
            const float bx = bias[col], by = bias[col + 1];
            float2 o0 = make_float2(acc[i][j][0] + bx, acc[i][j][1] + by);
            float2 o1 = make_float2(acc[i][j][2] + bx, acc[i][j][3] + by);
            *(float2*)(out + row0 * DIM_ + col) = o0;
            *(float2*)(out + (row0 + 8) * DIM_ + col) = o1;
        }
    }
}

// ---------------------------------------------------------------------------
// Sparse attention v2: coalesced warp-per-candidate score gather.
// Block = (n, b), 256 threads / 8 warps.
// Phase 1: warp w scores candidates {w, w+8, w+16, w+24}: lanes load the full
//          512-float k-row coalesced (lane l -> float4 j*32+l), per-head
//          partials reduced in 16-lane groups (head of p[j] = 2j + lane/16).
// Phase 2: warp h = softmax over 32 candidates of head h (scores in smem).
// Phase 3: warp h accumulates V (coalesced float2 per lane), as before.
// ---------------------------------------------------------------------------
__global__ __launch_bounds__(256, 6)
void attn_kernel(const float* __restrict__ qh, const float* __restrict__ kh,
                 const float* __restrict__ vh, const int* __restrict__ rns,
                 float* __restrict__ out) {
    __shared__ float sq[DIM_];
    __shared__ int srow[TOPK_];
    __shared__ int svrow[TOPK_];          // deduped global row or -1
    __shared__ float sscore[NH_][TOPK_];

    const int n = blockIdx.x;
    const int b = blockIdx.y;
    const int tid = threadIdx.x;
    const int lane = tid & 31;
    const int wid = tid >> 5;

    ((float2*)sq)[tid] = ((const float2*)(qh + (size_t)(n * BS_ + b) * DIM_))[tid];
    if (tid < TOPK_)
        srow[tid] = rns[((size_t)b * NP_ + n) * TOPK_ + tid];
    __syncthreads();
    if (tid < TOPK_) {
        const int m = srow[tid];
        bool valid = true;
        for (int j = 0; j < tid; j++)
            if (srow[j] == m) valid = false;
        svrow[tid] = valid ? (m * BS_ + b) : -1;
    }
    __syncthreads();

    // ---- Phase 1: scores ----
    const int g = lane >> 4;                 // 16-lane group: 0 or 1
#pragma unroll
    for (int cc = 0; cc < 4; cc++) {
        const int c = wid + cc * 8;
        const int r = svrow[c];
        float p[4] = {0.f, 0.f, 0.f, 0.f};
        if (r >= 0) {
            const float4* kp = (const float4*)(kh + (size_t)r * DIM_);
            const float4* qp = (const float4*)sq;
#pragma unroll
            for (int j = 0; j < 4; j++) {
                const float4 kv = kp[j * 32 + lane];
                const float4 qv = qp[j * 32 + lane];
                float a;
                a = kv.x * qv.x;
                a = fmaf(kv.y, qv.y, a);
                a = fmaf(kv.z, qv.z, a);
                a = fmaf(kv.w, qv.w, a);
                p[j] = a;
            }
        }
#pragma unroll
        for (int j = 0; j < 4; j++) {
            p[j] += __shfl_xor_sync(0xffffffffu, p[j], 8);
            p[j] += __shfl_xor_sync(0xffffffffu, p[j], 4);
            p[j] += __shfl_xor_sync(0xffffffffu, p[j], 2);
            p[j] += __shfl_xor_sync(0xffffffffu, p[j], 1);
        }
        if ((lane & 15) == 0) {
#pragma unroll
            for (int j = 0; j < 4; j++)
                sscore[2 * j + g][c] = (r >= 0) ? p[j] * 0.125f : -INFINITY;
        }
    }
    __syncthreads();

    // ---- Phase 2: per-head softmax (warp = head, lane = candidate) ----
    const int h = wid;
    const float s = sscore[h][lane];
    float mx = s;
#pragma unroll
    for (int o = 16; o; o >>= 1)
        mx = fmaxf(mx, __shfl_xor_sync(0xffffffffu, mx, o));
    float p = (s > -1e30f) ? __expf(s - mx) : 0.f;
    float sum = p;
#pragma unroll
    for (int o = 16; o; o >>= 1)
        sum += __shfl_xor_sync(0xffffffffu, sum, o);
    const float w = p / sum;

    // ---- Phase 3: V accumulate ----
    const int rl = svrow[lane];
    float2 acc2 = make_float2(0.f, 0.f);
#pragma unroll
    for (int t = 0; t < TOPK_; t++) {
        const float wt = __shfl_sync(0xffffffffu, w, t);
        const int r = __shfl_sync(0xffffffffu, rl, t);
        if (r >= 0) {
            const float2 vv =
                *(const float2*)(vh + (size_t)r * DIM_ + h * DH_ + lane * 2);
            acc2.x = fmaf(wt, vv.x, acc2.x);
            acc2.y = fmaf(wt, vv.y, acc2.y);
        }
    }
    *(float2*)(out + (size_t)(n * BS_ + b) * DIM_ + h * DH_ + lane * 2) = acc2;
}

// ---------------------------------------------------------------------------
extern "C" void kernel_launch(void* const* d_in, const int* in_sizes, int n_in,
                              void* d_out, int out_size) {
    const float* q   = (const float*)d_in[0];
    const float* k   = (const float*)d_in[1];
    const float* v   = (const float*)d_in[2];
    const int*   rns = (const int*)d_in[3];
    const float* W1  = (const float*)d_in[4];
    const float* b1  = (const float*)d_in[5];
    const float* W2  = (const float*)d_in[6];
    const float* b2  = (const float*)d_in[7];
    const float* W3  = (const float*)d_in[8];
    const float* b3  = (const float*)d_in[9];
    float* out = (float*)d_out;

    __nv_bfloat16 *ahi, *alo, *whi, *wlo;
    float* proj;
    cudaGetSymbolAddress((void**)&ahi, g_ahi);
    cudaGetSymbolAddress((void**)&alo, g_alo);
    cudaGetSymbolAddress((void**)&whi, g_whi);
    cudaGetSymbolAddress((void**)&wlo, g_wlo);
    cudaGetSymbolAddress((void**)&proj, g_proj);

    cudaFuncSetAttribute(gemm_mma, cudaFuncAttributeMaxDynamicSharedMemorySize,
                         GEMM_SMEM);

    const size_t offK = (size_t)MROWS_Q * DIM_;
    const size_t offV = offK + (size_t)MROWS_KV * DIM_;

    split_all<<<(R_W3 + 255) / 256, 256>>>(q, k, v, W1, W2, W3, ahi, alo, whi, wlo);

    gemm_mma<<<dim3(4, 288), 256, GEMM_SMEM>>>(ahi, alo, whi, wlo, b1, b2, b3, proj);

    attn_kernel<<<dim3(NP_, BS_), 256>>>(proj, proj + offK, proj + offV, rns, out);
}

// round 8
// speedup vs baseline: 1.5409x; 1.5409x over previous
#include <cuda_runtime.h>
#include <cuda_bf16.h>
#include <math.h>
#include <stdint.h>

// Problem constants
#define NP_   1024
#define MNP_  4096
#define BS_   4
#define DIM_  512
#define NH_   8
#define DH_   64
#define TOPK_ 32

#define MROWS_Q  (NP_*BS_)                 // 4096
#define MROWS_KV (MNP_*BS_)                // 16384
#define MTOT     (MROWS_Q + 2*MROWS_KV)    // 36864

// ---------------------------------------------------------------------------
// Scratch (device globals; no allocation allowed)
// ---------------------------------------------------------------------------
__device__ __nv_bfloat16 g_ahi[(size_t)MTOT * DIM_];
__device__ __nv_bfloat16 g_alo[(size_t)MTOT * DIM_];
__device__ __nv_bfloat16 g_whi[3 * DIM_ * DIM_];
__device__ __nv_bfloat16 g_wlo[3 * DIM_ * DIM_];
__device__ float         g_proj[(size_t)MTOT * DIM_];

// ---------------------------------------------------------------------------
// Helpers
// ---------------------------------------------------------------------------
__device__ __forceinline__ uint32_t smem_u32(const void* p) {
    uint32_t a;
    asm("{ .reg .u64 t; cvta.to.shared.u64 t, %1; cvt.u32.u64 %0, t; }"
        : "=r"(a) : "l"(p));
    return a;
}

__device__ __forceinline__ void cp16(uint32_t dst, const void* src) {
    asm volatile("cp.async.cg.shared.global [%0], [%1], 16;\n"
                 :: "r"(dst), "l"(src) : "memory");
}

__device__ __forceinline__ uint32_t swz(uint32_t o) { return o ^ ((o >> 3) & 0x70); }

__device__ __forceinline__ void ldsm4(uint32_t* f, uint32_t addr) {
    asm volatile("ldmatrix.sync.aligned.m8n8.x4.shared.b16 {%0,%1,%2,%3}, [%4];"
                 : "=r"(f[0]), "=r"(f[1]), "=r"(f[2]), "=r"(f[3]) : "r"(addr));
}

__device__ __forceinline__ void mma16816(float* d, const uint32_t* a,
                                         const uint32_t* b) {
    asm volatile(
        "mma.sync.aligned.m16n8k16.row.col.f32.bf16.bf16.f32 "
        "{%0,%1,%2,%3}, {%4,%5,%6,%7}, {%8,%9}, {%0,%1,%2,%3};"
        : "+f"(d[0]), "+f"(d[1]), "+f"(d[2]), "+f"(d[3])
        : "r"(a[0]), "r"(a[1]), "r"(a[2]), "r"(a[3]), "r"(b[0]), "r"(b[1]));
}

// ---------------------------------------------------------------------------
// Fused split: fp32 -> (bf16 hi, bf16 lo); q|k|v -> g_ahi/g_alo and
// W1|W2|W3 -> g_whi/g_wlo. Each thread handles 2 consecutive float4s
// (all region boundaries are even in float4 units).
// ---------------------------------------------------------------------------
#define R_Q  (MROWS_Q * DIM_ / 4)                 // 524288
#define R_K  (R_Q + MROWS_KV * DIM_ / 4)          // 2621440
#define R_V  (R_K + MROWS_KV * DIM_ / 4)          // 4718592
#define R_W1 (R_V + DIM_ * DIM_ / 4)
#define R_W2 (R_W1 + DIM_ * DIM_ / 4)
#define R_W3 (R_W2 + DIM_ * DIM_ / 4)             // 4915200 total

__global__ __launch_bounds__(256)
void split_all(const float* __restrict__ q, const float* __restrict__ k,
               const float* __restrict__ v, const float* __restrict__ W1,
               const float* __restrict__ W2, const float* __restrict__ W3,
               __nv_bfloat16* __restrict__ ahi, __nv_bfloat16* __restrict__ alo,
               __nv_bfloat16* __restrict__ whi, __nv_bfloat16* __restrict__ wlo) {
    const int i = (blockIdx.x * 256 + threadIdx.x) * 2;   // float4 index
    if (i >= R_W3) return;
    const float* src;
    __nv_bfloat16 *dh, *dl;
    size_t si, di;
    if (i < R_V) {
        di = (size_t)i;
        dh = ahi; dl = alo;
        if (i < R_Q)      { src = q; si = (size_t)i; }
        else if (i < R_K) { src = k; si = (size_t)(i - R_Q); }
        else              { src = v; si = (size_t)(i - R_K); }
    } else {
        di = (size_t)(i - R_V);
        dh = whi; dl = wlo;
        if (i < R_W1)      { src = W1; si = (size_t)(i - R_V); }
        else if (i < R_W2) { src = W2; si = (size_t)(i - R_W1); }
        else               { src = W3; si = (size_t)(i - R_W2); }
    }
    float4 x0 = ((const float4*)src)[si];
    float4 x1 = ((const float4*)src)[si + 1];
    float val[8] = {x0.x, x0.y, x0.z, x0.w, x1.x, x1.y, x1.z, x1.w};
    __nv_bfloat16 h[8], l[8];
#pragma unroll
    for (int j = 0; j < 8; j++) {
        h[j] = __float2bfloat16(val[j]);
        l[j] = __float2bfloat16(val[j] - __bfloat162float(h[j]));
    }
    *(uint4*)(dh + 4 * di) = *(uint4*)h;
    *(uint4*)(dl + 4 * di) = *(uint4*)l;
}

// ---------------------------------------------------------------------------
// mma.sync split-bf16 GEMM (unchanged): out = A*W^T + bias
// ---------------------------------------------------------------------------
#define KC       64
#define NCHUNK   24
#define STAGES   3
#define A_BYTES  (128 * 128)
#define B_BYTES  (128 * 128)
#define STG_B    (A_BYTES + B_BYTES)
#define GEMM_SMEM (STAGES * STG_B)           // 96KB

__global__ __launch_bounds__(256)
void gemm_mma(const __nv_bfloat16* __restrict__ ahi,
              const __nv_bfloat16* __restrict__ alo,
              const __nv_bfloat16* __restrict__ whi,
              const __nv_bfloat16* __restrict__ wlo,
              const float* __restrict__ b1, const float* __restrict__ b2,
              const float* __restrict__ b3, float* __restrict__ out) {
    extern __shared__ __align__(1024) char smem[];
    const uint32_t sbase = smem_u32(smem);
    const int tid = threadIdx.x;
    const int wid = tid >> 5;
    const int lane = tid & 31;
    const int wm = wid & 3;
    const int wn = wid >> 2;

    const int n0blk = blockIdx.x * 128;
    const int mt = blockIdx.y;
    const int widx = (mt < 32) ? 0 : (mt < 160) ? 1 : 2;
    const float* bias = (widx == 0) ? b1 : (widx == 1) ? b2 : b3;
    const __nv_bfloat16* Whi = whi + (size_t)widx * DIM_ * DIM_;
    const __nv_bfloat16* Wlo = wlo + (size_t)widx * DIM_ * DIM_;
    const size_t arow0 = (size_t)mt * 128;

    float acc[2][8][4];
#pragma unroll
    for (int i = 0; i < 2; i++)
#pragma unroll
        for (int j = 0; j < 8; j++)
#pragma unroll
            for (int r = 0; r < 4; r++) acc[i][j][r] = 0.f;

    auto load_chunk = [&](int c, int s) {
        const int t  = c >> 3;
        const int kk = (c & 7) * KC;
        const __nv_bfloat16* Ap = (t < 2) ? ahi : alo;
        const __nv_bfloat16* Bp = (t == 1) ? Wlo : Whi;
        const uint32_t a_s = sbase + s * STG_B;
        const uint32_t b_s = a_s + A_BYTES;
#pragma unroll
        for (int i = 0; i < 4; i++) {
            int u = tid + (i << 8);
            int r = u >> 3, j = u & 7;
            cp16(a_s + swz(r * 128 + j * 16),
                 Ap + (arow0 + r) * DIM_ + kk + j * 8);
        }
#pragma unroll
        for (int i = 0; i < 4; i++) {
            int u = tid + (i << 8);
            int r = u >> 3, j = u & 7;
            cp16(b_s + swz(r * 128 + j * 16),
                 Bp + (size_t)(n0blk + r) * DIM_ + kk + j * 8);
        }
        asm volatile("cp.async.commit_group;\n" ::: "memory");
    };

    load_chunk(0, 0);
    load_chunk(1, 1);

    const int a_row = wm * 32 + (lane & 15);
    const int a_ch  = (lane >> 4);
    const int b_row = wn * 64 + (lane & 7) + ((lane >> 4) << 3);
    const int b_ch  = ((lane >> 3) & 1);

#pragma unroll 1
    for (int c = 0; c < NCHUNK; ++c) {
        const int s = c % STAGES;
        if (c == NCHUNK - 1)
            asm volatile("cp.async.wait_group 0;\n" ::: "memory");
        else
            asm volatile("cp.async.wait_group 1;\n" ::: "memory");
        __syncthreads();
        if (c + 2 < NCHUNK) load_chunk(c + 2, (c + 2) % STAGES);

        const uint32_t a_s = sbase + s * STG_B;
        const uint32_t b_s = a_s + A_BYTES;
#pragma unroll
        for (int ks = 0; ks < 4; ks++) {
            const int c0 = ks * 2;
            uint32_t af[2][4];
#pragma unroll
            for (int i = 0; i < 2; i++)
                ldsm4(af[i], a_s + swz((a_row + i * 16) * 128 + (c0 + a_ch) * 16));
            uint32_t bf[4][4];
#pragma unroll
            for (int j = 0; j < 4; j++)
                ldsm4(bf[j], b_s + swz((b_row + j * 16) * 128 + (c0 + b_ch) * 16));
#pragma unroll
            for (int i = 0; i < 2; i++)
#pragma unroll
                for (int j = 0; j < 4; j++) {
                    mma16816(acc[i][2 * j],     af[i], &bf[j][0]);
                    mma16816(acc[i][2 * j + 1], af[i], &bf[j][2]);
                }
        }
    }

    const int lr = lane >> 2;
    const int lc = (lane & 3) * 2;
#pragma unroll
    for (int i = 0; i < 2; i++) {
        const size_t row0 = arow0 + wm * 32 + i * 16 + lr;
#pragma unroll
        for (int j = 0; j < 8; j++) {
            const int col = n0blk + wn * 64 + j * 8 + lc;
            const float bx = bias[col], by = bias[col + 1];
            float2 o0 = make_float2(acc[i][j][0] + bx, acc[i][j][1] + by);
            float2 o1 = make_float2(acc[i][j][2] + bx, acc[i][j][3] + by);
            *(float2*)(out + row0 * DIM_ + col) = o0;
            *(float2*)(out + (row0 + 8) * DIM_ + col) = o1;
        }
    }
}

// ---------------------------------------------------------------------------
// Sparse attention v2 (coalesced warp-per-candidate gather), WITHOUT the
// register-capping launch_bounds that caused spills in R7.
// ---------------------------------------------------------------------------
__global__ __launch_bounds__(256)
void attn_kernel(const float* __restrict__ qh, const float* __restrict__ kh,
                 const float* __restrict__ vh, const int* __restrict__ rns,
                 float* __restrict__ out) {
    __shared__ float sq[DIM_];
    __shared__ int srow[TOPK_];
    __shared__ int svrow[TOPK_];          // deduped global row or -1
    __shared__ float sscore[NH_][TOPK_];

    const int n = blockIdx.x;
    const int b = blockIdx.y;
    const int tid = threadIdx.x;
    const int lane = tid & 31;
    const int wid = tid >> 5;

    ((float2*)sq)[tid] = ((const float2*)(qh + (size_t)(n * BS_ + b) * DIM_))[tid];
    if (tid < TOPK_)
        srow[tid] = rns[((size_t)b * NP_ + n) * TOPK_ + tid];
    __syncthreads();
    if (tid < TOPK_) {
        const int m = srow[tid];
        bool valid = true;
        for (int j = 0; j < tid; j++)
            if (srow[j] == m) valid = false;
        svrow[tid] = valid ? (m * BS_ + b) : -1;
    }
    __syncthreads();

    // ---- Phase 1: scores (warp w covers candidates w, w+8, w+16, w+24) ----
    const int g = lane >> 4;                 // 16-lane group: 0 or 1
#pragma unroll
    for (int cc = 0; cc < 4; cc++) {
        const int c = wid + cc * 8;
        const int r = svrow[c];
        float p[4] = {0.f, 0.f, 0.f, 0.f};
        if (r >= 0) {
            const float4* kp = (const float4*)(kh + (size_t)r * DIM_);
            const float4* qp = (const float4*)sq;
#pragma unroll
            for (int j = 0; j < 4; j++) {
                const float4 kv = kp[j * 32 + lane];
                const float4 qv = qp[j * 32 + lane];
                float a;
                a = kv.x * qv.x;
                a = fmaf(kv.y, qv.y, a);
                a = fmaf(kv.z, qv.z, a);
                a = fmaf(kv.w, qv.w, a);
                p[j] = a;
            }
        }
#pragma unroll
        for (int j = 0; j < 4; j++) {
            p[j] += __shfl_xor_sync(0xffffffffu, p[j], 8);
            p[j] += __shfl_xor_sync(0xffffffffu, p[j], 4);
            p[j] += __shfl_xor_sync(0xffffffffu, p[j], 2);
            p[j] += __shfl_xor_sync(0xffffffffu, p[j], 1);
        }
        if ((lane & 15) == 0) {
#pragma unroll
            for (int j = 0; j < 4; j++)
                sscore[2 * j + g][c] = (r >= 0) ? p[j] * 0.125f : -INFINITY;
        }
    }
    __syncthreads();

    // ---- Phase 2: per-head softmax (warp = head, lane = candidate) ----
    const int h = wid;
    const float s = sscore[h][lane];
    float mx = s;
#pragma unroll
    for (int o = 16; o; o >>= 1)
        mx = fmaxf(mx, __shfl_xor_sync(0xffffffffu, mx, o));
    float p = (s > -1e30f) ? __expf(s - mx) : 0.f;
    float sum = p;
#pragma unroll
    for (int o = 16; o; o >>= 1)
        sum += __shfl_xor_sync(0xffffffffu, sum, o);
    const float w = p / sum;

    // ---- Phase 3: V accumulate (coalesced) ----
    const int rl = svrow[lane];
    float2 acc2 = make_float2(0.f, 0.f);
#pragma unroll
    for (int t = 0; t < TOPK_; t++) {
        const float wt = __shfl_sync(0xffffffffu, w, t);
        const int r = __shfl_sync(0xffffffffu, rl, t);
        if (r >= 0) {
            const float2 vv =
                *(const float2*)(vh + (size_t)r * DIM_ + h * DH_ + lane * 2);
            acc2.x = fmaf(wt, vv.x, acc2.x);
            acc2.y = fmaf(wt, vv.y, acc2.y);
        }
    }
    *(float2*)(out + (size_t)(n * BS_ + b) * DIM_ + h * DH_ + lane * 2) = acc2;
}

// ---------------------------------------------------------------------------
extern "C" void kernel_launch(void* const* d_in, const int* in_sizes, int n_in,
                              void* d_out, int out_size) {
    const float* q   = (const float*)d_in[0];
    const float* k   = (const float*)d_in[1];
    const float* v   = (const float*)d_in[2];
    const int*   rns = (const int*)d_in[3];
    const float* W1  = (const float*)d_in[4];
    const float* b1  = (const float*)d_in[5];
    const float* W2  = (const float*)d_in[6];
    const float* b2  = (const float*)d_in[7];
    const float* W3  = (const float*)d_in[8];
    const float* b3  = (const float*)d_in[9];
    float* out = (float*)d_out;

    __nv_bfloat16 *ahi, *alo, *whi, *wlo;
    float* proj;
    cudaGetSymbolAddress((void**)&ahi, g_ahi);
    cudaGetSymbolAddress((void**)&alo, g_alo);
    cudaGetSymbolAddress((void**)&whi, g_whi);
    cudaGetSymbolAddress((void**)&wlo, g_wlo);
    cudaGetSymbolAddress((void**)&proj, g_proj);

    cudaFuncSetAttribute(gemm_mma, cudaFuncAttributeMaxDynamicSharedMemorySize,
                         GEMM_SMEM);

    const size_t offK = (size_t)MROWS_Q * DIM_;
    const size_t offV = offK + (size_t)MROWS_KV * DIM_;

    split_all<<<(R_W3 / 2 + 255) / 256, 256>>>(q, k, v, W1, W2, W3,
                                               ahi, alo, whi, wlo);

    gemm_mma<<<dim3(4, 288), 256, GEMM_SMEM>>>(ahi, alo, whi, wlo, b1, b2, b3, proj);

    attn_kernel<<<dim3(NP_, BS_), 256>>>(proj, proj + offK, proj + offV, rns, out);
}